// round 1
// baseline (speedup 1.0000x reference)
#include <cuda_runtime.h>
#include <cstddef>

// Problem constants: B=4, C=64, H=W=256
#define HW_ 65536

typedef unsigned long long u64;

// Scratch (no cudaMalloc allowed) — 3 x 67MB feature buffers + stats
__device__ float g_h [16777216];
__device__ float g_t1[16777216];
__device__ float g_t2[16777216];
__device__ float g_mean[256];
__device__ float g_rstd[256];

// ---------- packed f32x2 helpers ----------
__device__ __forceinline__ u64 pk2(float lo, float hi) {
    u64 r;
    asm("mov.b64 %0, {%1, %2};" : "=l"(r)
        : "r"(__float_as_uint(lo)), "r"(__float_as_uint(hi)));
    return r;
}
__device__ __forceinline__ float2 upk(u64 v) {
    unsigned lo, hi;
    asm("mov.b64 {%0, %1}, %2;" : "=r"(lo), "=r"(hi) : "l"(v));
    return make_float2(__uint_as_float(lo), __uint_as_float(hi));
}
__device__ __forceinline__ u64 fma2(u64 a, u64 b, u64 c) {
    u64 d;
    asm("fma.rn.f32x2 %0, %1, %2, %3;" : "=l"(d) : "l"(a), "l"(b), "l"(c));
    return d;
}
__device__ __forceinline__ u64 mul2(u64 a, u64 b) {
    u64 d;
    asm("mul.rn.f32x2 %0, %1, %2;" : "=l"(d) : "l"(a), "l"(b));
    return d;
}

// reflect-pad index for pad=1, n=256
__device__ __forceinline__ int reflx(int i) {
    return i < 0 ? 1 : (i >= 256 ? 254 : i);
}

// ---------- 1x1 input conv: h[b,o,:,:] = w0[o]*x[b,0,:,:] + b0[o] ----------
__global__ void conv1x1_kernel(const float* __restrict__ x,
                               const float* __restrict__ w0,
                               const float* __restrict__ b0,
                               float* __restrict__ h)
{
    __shared__ float sw[64], sb[64];
    int tid = threadIdx.x;
    if (tid < 64) { sw[tid] = w0[tid]; sb[tid] = b0[tid]; }
    __syncthreads();
    int p = blockIdx.x * 256 + tid;           // 0 .. 4*65536-1
    int b = p >> 16;
    int pos = p & 65535;
    float xv = x[p];
#pragma unroll
    for (int o = 0; o < 64; ++o) {
        h[(((size_t)(b * 64 + o)) << 16) + pos] = fmaf(sw[o], xv, sb[o]);
    }
}

// ---------- instance-norm stats: mean / rstd per (b,c) ----------
__global__ void stats_kernel(const float* __restrict__ src,
                             float* __restrict__ meanv,
                             float* __restrict__ rstdv)
{
    int bc = blockIdx.x;                      // 0..255
    const float* p = src + ((size_t)bc << 16);
    int tid = threadIdx.x;
    float s = 0.f, q = 0.f;
    for (int i = tid; i < HW_; i += 256) {
        float v = p[i];
        s += v;
        q = fmaf(v, v, q);
    }
    __shared__ float ss[256], sq[256];
    ss[tid] = s; sq[tid] = q;
    __syncthreads();
    for (int off = 128; off > 0; off >>= 1) {
        if (tid < off) { ss[tid] += ss[tid + off]; sq[tid] += sq[tid + off]; }
        __syncthreads();
    }
    if (tid == 0) {
        float m   = ss[0] * (1.0f / 65536.0f);
        float var = sq[0] * (1.0f / 65536.0f) - m * m;
        meanv[bc] = m;
        rstdv[bc] = rsqrtf(var + 1e-5f);
    }
}

// ---------- residual combine: h = relu(h + (t2-mean)*rstd) ----------
__global__ void combine_kernel(float* __restrict__ h,
                               const float* __restrict__ t2,
                               const float* __restrict__ meanv,
                               const float* __restrict__ rstdv)
{
    size_t i = (size_t)blockIdx.x * 256 + threadIdx.x;    // 16,777,216 total
    int bc = (int)(i >> 16);
    float v = (t2[i] - meanv[bc]) * rstdv[bc];
    h[i] = fmaxf(h[i] + v, 0.f);
}

// ---------- pixel-adaptive 3x3 conv (the hot kernel) ----------
// Block = one output row (b, y): 64 oc x 256 px.
// Thread tile: 8 oc x 8 px (4 f32x2 pairs). 8 warps: warp -> oc group, lane -> px pair.
// NORM_IN:   normalize+relu input while loading into smem (conv-b of each resblock)
// USE_K:     apply per-pixel Gaussian guide kernel (false for the final plain conv)
// FINAL_RELU: epilogue relu (final conv); otherwise plain acc+bias.
template <bool NORM_IN, bool USE_K, bool FINAL_RELU>
__global__ void __launch_bounds__(256)
pac_conv_kernel(const float* __restrict__ in,
                const float* __restrict__ guide,
                const float* __restrict__ w,       // [64][64][3][3]
                const float* __restrict__ bias,    // [64]
                const float* __restrict__ meanv,
                const float* __restrict__ rstdv,
                float* __restrict__ out)
{
    const int y    = blockIdx.x;     // 0..255
    const int b    = blockIdx.y;     // 0..3
    const int tid  = threadIdx.x;
    const int warp = tid >> 5;
    const int lane = tid & 31;
    const int oc_base = warp << 3;   // 8 oc per warp
    const int px0     = lane << 1;   // pair base within 64-px group

    // shared layout (46272 B static):
    //  [0      : 9216 )  s_k  : float [9][256]    (guide kernel per tap per px)
    //  [9216   : 33984)  s_in : float [3][8][258] (3 ky rows x 8-ch chunk, reflect-padded)
    //  [33984  : 46272)  s_w2 : u64   [8][3][64]  (weights duplicated {w,w})
    //  s_g overlays s_w2 (only used before first s_w2 load)
    __shared__ __align__(16) unsigned char sraw[46272];
    float (*s_k)[256]     = reinterpret_cast<float(*)[256]>(sraw);
    float (*s_in)[8][258] = reinterpret_cast<float(*)[8][258]>(sraw + 9216);
    u64   (*s_w2)[3][64]  = reinterpret_cast<u64(*)[3][64]>(sraw + 33984);
    float (*s_g)[258]     = reinterpret_cast<float(*)[258]>(sraw + 33984);

    int yy[3];
    yy[0] = (y == 0)   ? 1   : y - 1;
    yy[1] = y;
    yy[2] = (y == 255) ? 254 : y + 1;

    if (USE_K) {
        // load 3 guide rows (reflect-padded, C=1), then build k for all 9 taps
        const float* gpl = guide + ((size_t)b << 16);
        for (int idx = tid; idx < 3 * 258; idx += 256) {
            int r  = idx / 258;
            int sx = idx - r * 258;
            int gx = reflx(sx - 1);
            s_g[r][sx] = gpl[yy[r] * 256 + gx];
        }
        __syncthreads();
        for (int it = 0; it < 9; ++it) {
            int tap = it;          // one tap per iteration, px = tid
            int px  = tid;
            float d = s_g[tap / 3][px + tap % 3] - s_g[1][px + 1];
            s_k[tap][px] = __expf(-0.5f * d * d);
        }
    }

    u64 acc[8][4];
#pragma unroll
    for (int o = 0; o < 8; ++o)
#pragma unroll
        for (int j = 0; j < 4; ++j) acc[o][j] = 0ULL;

    for (int cc = 0; cc < 8; ++cc) {          // 8 channel chunks of 8
        const int c0 = cc << 3;
        __syncthreads();                      // prev chunk compute done
        // load input rows for this chunk (reflect-padded), optional norm+relu
        for (int idx = tid; idx < 3 * 8 * 258; idx += 256) {
            int r   = idx / (8 * 258);
            int rem = idx - r * (8 * 258);
            int ci  = rem / 258;
            int sx  = rem - ci * 258;
            int gx  = reflx(sx - 1);
            int c   = c0 + ci;
            float v = in[(((size_t)(b * 64 + c)) << 16) + yy[r] * 256 + gx];
            if (NORM_IN) {
                v = fmaxf((v - meanv[b * 64 + c]) * rstdv[b * 64 + c], 0.f);
            }
            s_in[r][ci][sx] = v;
        }

#pragma unroll
        for (int ky = 0; ky < 3; ++ky) {
            __syncthreads();                  // s_in ready (ky=0) / s_w2 reusable
            // stage weights for (chunk, ky, all kx), duplicated into u64
            for (int idx = tid; idx < 1536; idx += 256) {
                int ci  = idx / 192;
                int rem = idx - ci * 192;
                int kx  = rem >> 6;
                int o   = rem & 63;
                float wv = w[(o * 64 + c0 + ci) * 9 + ky * 3 + kx];
                s_w2[ci][kx][o] = pk2(wv, wv);
            }
            __syncthreads();

            u64 kk[3][4];
            if (USE_K) {
#pragma unroll
                for (int kx = 0; kx < 3; ++kx)
#pragma unroll
                    for (int j = 0; j < 4; ++j)
                        kk[kx][j] = *reinterpret_cast<const u64*>(
                            &s_k[ky * 3 + kx][(j << 6) + px0]);
            }

#pragma unroll
            for (int ci = 0; ci < 8; ++ci) {
                const float* srow = s_in[ky][ci];
                u64 vk[3][4];
#pragma unroll
                for (int j = 0; j < 4; ++j) {
                    int sx = (j << 6) + px0;
                    u64 v0 = *reinterpret_cast<const u64*>(&srow[sx]);     // cols sx, sx+1
                    u64 v2 = *reinterpret_cast<const u64*>(&srow[sx + 2]); // cols sx+2, sx+3
                    u64 v1 = (v0 >> 32) | (v2 << 32);                      // cols sx+1, sx+2
                    if (USE_K) {
                        vk[0][j] = mul2(v0, kk[0][j]);
                        vk[1][j] = mul2(v1, kk[1][j]);
                        vk[2][j] = mul2(v2, kk[2][j]);
                    } else {
                        vk[0][j] = v0; vk[1][j] = v1; vk[2][j] = v2;
                    }
                }
#pragma unroll
                for (int o = 0; o < 8; ++o) {
#pragma unroll
                    for (int kx = 0; kx < 3; ++kx) {
                        u64 w2v = s_w2[ci][kx][oc_base + o];  // LDS.64 broadcast
#pragma unroll
                        for (int j = 0; j < 4; ++j)
                            acc[o][j] = fma2(vk[kx][j], w2v, acc[o][j]);
                    }
                }
            }
        }
    }

    // epilogue: + bias (, relu), vectorized float2 stores
#pragma unroll
    for (int o = 0; o < 8; ++o) {
        float bv = bias[oc_base + o];
        float* op = out + (((size_t)(b * 64 + oc_base + o)) << 16) + y * 256;
#pragma unroll
        for (int j = 0; j < 4; ++j) {
            float2 r = upk(acc[o][j]);
            r.x += bv; r.y += bv;
            if (FINAL_RELU) { r.x = fmaxf(r.x, 0.f); r.y = fmaxf(r.y, 0.f); }
            *reinterpret_cast<float2*>(&op[(j << 6) + px0]) = r;
        }
    }
}

// ---------- launcher ----------
extern "C" void kernel_launch(void* const* d_in, const int* in_sizes, int n_in,
                              void* d_out, int out_size)
{
    (void)in_sizes; (void)n_in; (void)out_size;
    // metadata order: x, grad_img(unused), w0, b0, wf, bf,
    //                 w1a,b1a,w1b,b1b, w2a,b2a,w2b,b2b, w3a,b3a,w3b,b3b
    const float* x  = (const float*)d_in[0];
    const float* w0 = (const float*)d_in[2];
    const float* b0 = (const float*)d_in[3];
    const float* wf = (const float*)d_in[4];
    const float* bf = (const float*)d_in[5];
    const float* wa[3] = {(const float*)d_in[6],  (const float*)d_in[10], (const float*)d_in[14]};
    const float* ba[3] = {(const float*)d_in[7],  (const float*)d_in[11], (const float*)d_in[15]};
    const float* wb[3] = {(const float*)d_in[8],  (const float*)d_in[12], (const float*)d_in[16]};
    const float* bb[3] = {(const float*)d_in[9],  (const float*)d_in[13], (const float*)d_in[17]};

    float *h, *t1, *t2, *mv, *rv;
    cudaGetSymbolAddress((void**)&h,  g_h);
    cudaGetSymbolAddress((void**)&t1, g_t1);
    cudaGetSymbolAddress((void**)&t2, g_t2);
    cudaGetSymbolAddress((void**)&mv, g_mean);
    cudaGetSymbolAddress((void**)&rv, g_rstd);

    dim3 pg(256, 4);   // (row y, batch b)

    conv1x1_kernel<<<1024, 256>>>(x, w0, b0, h);

    for (int r = 0; r < 3; ++r) {
        // conv-a: plain input, guided kernel, raw output
        pac_conv_kernel<false, true, false><<<pg, 256>>>(h, x, wa[r], ba[r],
                                                         nullptr, nullptr, t1);
        stats_kernel<<<256, 256>>>(t1, mv, rv);
        // conv-b: input = relu(inorm(t1)) fused at load
        pac_conv_kernel<true, true, false><<<pg, 256>>>(t1, x, wb[r], bb[r],
                                                        mv, rv, t2);
        stats_kernel<<<256, 256>>>(t2, mv, rv);
        // h = relu(h + inorm(t2))
        combine_kernel<<<65536, 256>>>(h, t2, mv, rv);
    }

    // final plain 3x3 conv + bias + relu -> d_out
    pac_conv_kernel<false, false, true><<<pg, 256>>>(h, x, wf, bf,
                                                     nullptr, nullptr,
                                                     (float*)d_out);
}